// round 14
// baseline (speedup 1.0000x reference)
#include <cuda_runtime.h>

// Problem constants (fixed by the dataset)
#define B_    64
#define OBJS_ 2048
#define D_    256
#define K_    2
#define N_    (B_*OBJS_)          // 131072
#define BDK   (B_*D_*K_)          // 32768
#define NK    (N_*K_)             // 262144

#define WAVES 4
#define SPW   (B_/WAVES)          // 16 scenes per wave (32 MB)
#define CPS   16                  // CTAs per scene
#define NCTA  (SPW*CPS)           // 256 — co-resident at 2 CTAs/SM (296 slots)
#define CHUNK (OBJS_/CPS)         // 128 rows per CTA
#define THREADS 256
#define NWARP 8
#define RPW   (CHUNK/NWARP)       // 16 rows per warp

typedef unsigned long long u64;

// Scratch (device globals — allocation-free rule). Per-(scene,chunk) slots,
// plain stores each launch -> no zeroing needed, replay-safe.
__device__ float g_ctxp [B_*CPS*D_];     // column-sum partials (4 MB)
__device__ float g_featp[B_*CPS*D_*K_];  // pooled-feature partials (2 MB)
__device__ float g_zsump[B_*CPS*K_];     // zsum partials
__device__ int   g_bar[WAVES+1];         // grid-barrier counters
__device__ int   g_ack;                  // end-of-kernel ack (for reset)

// ---- packed f32x2 helpers --------------------------------------------------
__device__ __forceinline__ u64 pack2(float lo, float hi) {
    u64 r; asm("mov.b64 %0,{%1,%2};" : "=l"(r) : "f"(lo), "f"(hi)); return r;
}
__device__ __forceinline__ float2 unpack2(u64 v) {
    float lo, hi; asm("mov.b64 {%0,%1},%2;" : "=f"(lo), "=f"(hi) : "l"(v));
    return make_float2(lo, hi);
}
__device__ __forceinline__ u64 add2(u64 a, u64 b) {
    u64 d; asm("add.rn.f32x2 %0,%1,%2;" : "=l"(d) : "l"(a), "l"(b)); return d;
}
__device__ __forceinline__ u64 fma2(u64 a, u64 b, u64 c) {
    u64 d; asm("fma.rn.f32x2 %0,%1,%2,%3;" : "=l"(d) : "l"(a), "l"(b), "l"(c)); return d;
}
__device__ __forceinline__ u64 abs2(u64 a) {
    u64 d; asm("and.b64 %0,%1,0x7FFFFFFF7FFFFFFF;" : "=l"(d) : "l"(a)); return d;
}

// grid barrier: all NCTA CTAs co-resident by construction
__device__ __forceinline__ void gridbar(int i, int tid) {
    __threadfence();
    __syncthreads();
    if (tid == 0) {
        atomicAdd(&g_bar[i], 1);
        volatile int* c = &g_bar[i];
        while (*c < NCTA) __nanosleep(32);
    }
    __syncthreads();
}

// ---------------------------------------------------------------------------
__global__ __launch_bounds__(THREADS, 2) void fusedK(
    const float* __restrict__ x,
    const float* __restrict__ att,
    const float* __restrict__ scale,
    const float* __restrict__ cb,
    const int*   __restrict__ num_objs,
    float*       __restrict__ out,
    int out_size)
{
    __shared__ __align__(16) float sred[4*D_];      // p1 rowgroup partials (4 KB)
    __shared__ __align__(16) float sctx[D_];        // scene mean context
    __shared__ float sfeat[D_*K_];                  // feature accum (2 KB)
    __shared__ __align__(8) float sz[CHUNK*K_];     // per-row z (1 KB)
    __shared__ float sbt[K_];
    __shared__ float szs[K_];

    const int cta   = blockIdx.x;
    const int sidx  = cta >> 4;           // scene within wave
    const int chunk = cta & 15;
    const int tid   = threadIdx.x;
    const int warp  = tid >> 5, lane = tid & 31;
    const int col4  = tid & 63, rg = tid >> 6;      // p1 layout

    const bool full_out = (out_size >= BDK + NK);
    const bool attn_any = full_out || (out_size == NK);

    // bias_term (tiny, per-CTA redundant)
    if (tid < 64) {
        int k = tid >> 5, l = tid & 31;
        float s = 0.f;
        #pragma unroll
        for (int j = 0; j < 8; j++) s += cb[k*D_ + l + 32*j] * att[l + 32*j];
        #pragma unroll
        for (int m = 16; m; m >>= 1) s += __shfl_xor_sync(0xffffffffu, s, m);
        if (l == 0) sbt[k] = s;
    }

    // per-lane invariant att factors: lrelu(t)=0.6t+0.4|t|
    float4 a_a = ((const float4*)att)[lane];
    float4 a_b = ((const float4*)att)[lane + 32];
    const u64 a6_0 = pack2(0.6f*a_a.x, 0.6f*a_a.y), a6_1 = pack2(0.6f*a_a.z, 0.6f*a_a.w);
    const u64 a6_2 = pack2(0.6f*a_b.x, 0.6f*a_b.y), a6_3 = pack2(0.6f*a_b.z, 0.6f*a_b.w);
    const u64 a4_0 = pack2(0.4f*a_a.x, 0.4f*a_a.y), a4_1 = pack2(0.4f*a_a.z, 0.4f*a_a.w);
    const u64 a4_2 = pack2(0.4f*a_b.x, 0.4f*a_b.y), a4_3 = pack2(0.4f*a_b.z, 0.4f*a_b.w);

    // ================= PHASE A: p1 of wave 0 (batched, high MLP) ===========
    {
        const float4* p = (const float4*)x
            + ((size_t)(sidx*OBJS_ + chunk*CHUNK + rg))*64 + col4;
        float4 acc = {0.f,0.f,0.f,0.f};
        #pragma unroll
        for (int i = 0; i < 8; i++) {          // 32 loads, 4-deep batches
            float4 v0 = p[(size_t)(4*i+0)*256];
            float4 v1 = p[(size_t)(4*i+1)*256];
            float4 v2 = p[(size_t)(4*i+2)*256];
            float4 v3 = p[(size_t)(4*i+3)*256];
            acc.x += (v0.x+v1.x) + (v2.x+v3.x);
            acc.y += (v0.y+v1.y) + (v2.y+v3.y);
            acc.z += (v0.z+v1.z) + (v2.z+v3.z);
            acc.w += (v0.w+v1.w) + (v2.w+v3.w);
        }
        *(float4*)&sred[rg*D_ + col4*4] = acc;
    }
    __syncthreads();
    {
        float s = sred[tid] + sred[D_+tid] + sred[2*D_+tid] + sred[3*D_+tid];
        g_ctxp[(size_t)(sidx*CPS + chunk)*D_ + tid] = s;
    }
    gridbar(0, tid);

    const float bt0 = sbt[0], bt1 = sbt[1];
    const float s0  = scale[0], s1 = scale[1];

    // ================= wave loop: p2(w) interleaved with p1(w+1) ===========
    #pragma unroll 1
    for (int w = 0; w < WAVES; w++) {
        const int b = w*SPW + sidx;
        const bool pre = (w+1 < WAVES);

        // scene mean ctx from the 16 partials (L2-hot)
        {
            const float invc = 1.f / fmaxf((float)num_objs[b], 1.f);
            float s = 0.f;
            #pragma unroll
            for (int j = 0; j < CPS; j++) s += g_ctxp[(size_t)(b*CPS + j)*D_ + tid];
            sctx[tid] = s * invc;
        }
        for (int i = tid; i < D_*K_; i += THREADS) sfeat[i] = 0.f;
        if (tid < K_) szs[tid] = 0.f;
        __syncthreads();

        float4 cxa = ((const float4*)sctx)[lane];
        float4 cxb = ((const float4*)sctx)[lane + 32];
        u64 c0 = pack2(cxa.x, cxa.y), c1 = pack2(cxa.z, cxa.w);
        u64 c2 = pack2(cxb.x, cxb.y), c3 = pack2(cxb.z, cxb.w);

        // p1 pointer for wave w+1 (this CTA's same chunk in next wave)
        const float4* pn = (const float4*)x
            + ((size_t)((b+SPW)*OBJS_ + chunk*CHUNK + rg))*64 + col4;
        float4 nacc = {0.f,0.f,0.f,0.f};

        u64 f0_0=0,f0_1=0,f0_2=0,f0_3=0;
        u64 f1_0=0,f1_1=0,f1_2=0,f1_3=0;
        float zs0 = 0.f, zs1 = 0.f;

        const int rowbase = b*OBJS_ + chunk*CHUNK + warp*RPW;

        #pragma unroll 4
        for (int r = 0; r < RPW; r++) {
            // interleaved DRAM loads for next wave's column sums
            if (pre) {
                float4 v0 = pn[(size_t)(2*r  )*256];
                float4 v1 = pn[(size_t)(2*r+1)*256];
                nacc.x += v0.x + v1.x; nacc.y += v0.y + v1.y;
                nacc.z += v0.z + v1.z; nacc.w += v0.w + v1.w;
            }
            const int lrow = warp*RPW + r;
            const ulonglong2* xr = (const ulonglong2*)(x + (size_t)(rowbase + r)*D_);
            ulonglong2 xa = xr[lane];
            ulonglong2 xb = xr[lane + 32];

            u64 t0 = add2(xa.x, c0), t1 = add2(xa.y, c1);
            u64 t2 = add2(xb.x, c2), t3 = add2(xb.y, c3);
            u64 accA = fma2(a6_0, t0, fma2(a4_0, abs2(t0), 0ull));
            accA     = fma2(a6_1, t1, fma2(a4_1, abs2(t1), accA));
            u64 accB = fma2(a6_2, t2, fma2(a4_2, abs2(t2), 0ull));
            accB     = fma2(a6_3, t3, fma2(a4_3, abs2(t3), accB));
            float2 p = unpack2(add2(accA, accB));
            float acc = p.x + p.y;
            #pragma unroll
            for (int m = 16; m; m >>= 1)
                acc += __shfl_xor_sync(0xffffffffu, acc, m);

            float z0 = __expf((acc + bt0) * s0);
            float z1 = __expf((acc + bt1) * s1);
            zs0 += z0; zs1 += z1;
            if (lane == 0) *(float2*)&sz[lrow*2] = make_float2(z0, z1);

            u64 zz0 = pack2(z0, z0), zz1 = pack2(z1, z1);
            f0_0 = fma2(xa.x, zz0, f0_0); f0_1 = fma2(xa.y, zz0, f0_1);
            f0_2 = fma2(xb.x, zz0, f0_2); f0_3 = fma2(xb.y, zz0, f0_3);
            f1_0 = fma2(xa.x, zz1, f1_0); f1_1 = fma2(xa.y, zz1, f1_1);
            f1_2 = fma2(xb.x, zz1, f1_2); f1_3 = fma2(xb.y, zz1, f1_3);
        }

        // cross-warp combine (lanes hit distinct smem addrs within a warp)
        {
            int d0 = 4*lane, d1 = 128 + 4*lane;
            float2 v;
            v = unpack2(f0_0); atomicAdd(&sfeat[(d0+0)*2+0], v.x); atomicAdd(&sfeat[(d0+1)*2+0], v.y);
            v = unpack2(f0_1); atomicAdd(&sfeat[(d0+2)*2+0], v.x); atomicAdd(&sfeat[(d0+3)*2+0], v.y);
            v = unpack2(f0_2); atomicAdd(&sfeat[(d1+0)*2+0], v.x); atomicAdd(&sfeat[(d1+1)*2+0], v.y);
            v = unpack2(f0_3); atomicAdd(&sfeat[(d1+2)*2+0], v.x); atomicAdd(&sfeat[(d1+3)*2+0], v.y);
            v = unpack2(f1_0); atomicAdd(&sfeat[(d0+0)*2+1], v.x); atomicAdd(&sfeat[(d0+1)*2+1], v.y);
            v = unpack2(f1_1); atomicAdd(&sfeat[(d0+2)*2+1], v.x); atomicAdd(&sfeat[(d0+3)*2+1], v.y);
            v = unpack2(f1_2); atomicAdd(&sfeat[(d1+0)*2+1], v.x); atomicAdd(&sfeat[(d1+1)*2+1], v.y);
            v = unpack2(f1_3); atomicAdd(&sfeat[(d1+2)*2+1], v.x); atomicAdd(&sfeat[(d1+3)*2+1], v.y);
        }
        if (lane == 0) { atomicAdd(&szs[0], zs0); atomicAdd(&szs[1], zs1); }
        __syncthreads();

        // publish this wave's partials (plain stores)
        const int slot = b*CPS + chunk;
        for (int i = tid; i < D_*K_; i += THREADS)
            g_featp[(size_t)slot*(D_*K_) + i] = sfeat[i];
        if (tid < K_) g_zsump[slot*K_ + tid] = szs[tid];

        // publish next wave's column-sum partial
        if (pre) {
            *(float4*)&sred[rg*D_ + col4*4] = nacc;
            __syncthreads();
            float s = sred[tid] + sred[D_+tid] + sred[2*D_+tid] + sred[3*D_+tid];
            g_ctxp[(size_t)((b+SPW)*CPS + chunk)*D_ + tid] = s;
        }

        gridbar(1+w, tid);

        // ---- post-barrier: outputs for wave w (sz still holds wave-w z) ---
        float zt0 = 0.f, zt1 = 0.f;
        #pragma unroll
        for (int j = 0; j < CPS; j++) {
            zt0 += g_zsump[(b*CPS + j)*K_ + 0];
            zt1 += g_zsump[(b*CPS + j)*K_ + 1];
        }
        const float inv0 = 1.f/zt0, inv1 = 1.f/zt1;

        if (attn_any) {
            int obase = full_out ? (BDK/2) : 0;
            float2* o2 = ((float2*)out) + obase + b*OBJS_ + chunk*CHUNK;
            const float2* z2 = (const float2*)sz;
            for (int i = tid; i < CHUNK; i += THREADS) {
                float2 z = z2[i];
                o2[i] = make_float2(z.x*inv0, z.y*inv1);
            }
        }
        if (chunk == 0 && out_size >= BDK) {     // one finalizer CTA per scene
            for (int e = tid; e < D_*K_; e += THREADS) {
                float s = 0.f;
                #pragma unroll
                for (int j = 0; j < CPS; j++)
                    s += g_featp[(size_t)(b*CPS + j)*(D_*K_) + e];
                out[b*(D_*K_) + e] = s * ((e & 1) ? inv1 : inv0);
            }
        }
        // next iteration's __syncthreads (after ctx fill) orders sz reuse
    }

    // last CTA overall resets barrier counters for the next graph replay
    if (tid == 0) {
        int a = atomicAdd(&g_ack, 1);
        if (a == NCTA-1) {
            #pragma unroll
            for (int i = 0; i <= WAVES; i++) g_bar[i] = 0;
            g_ack = 0;
        }
    }
}

// ---------------------------------------------------------------------------
extern "C" void kernel_launch(void* const* d_in, const int* in_sizes, int n_in,
                              void* d_out, int out_size)
{
    const float* x        = (const float*)d_in[0];  // [N, D]
    const int*   num_objs = (const int*)  d_in[1];  // [B]
    const float* att      = (const float*)d_in[2];  // [1, D]
    const float* scale    = (const float*)d_in[3];  // [K, 1]
    const float* cb       = (const float*)d_in[4];  // [K, D]
    float*       out      = (float*)d_out;

    fusedK<<<NCTA, THREADS>>>(x, att, scale, cb, num_objs, out, out_size);
}

// round 16
// speedup vs baseline: 1.6919x; 1.6919x over previous
#include <cuda_runtime.h>

// Problem constants (fixed by the dataset)
#define B_    64
#define OBJS_ 2048
#define D_    256
#define K_    2
#define N_    (B_*OBJS_)          // 131072
#define BDK   (B_*D_*K_)          // 32768
#define NK    (N_*K_)             // 262144

#define WAVES 2
#define SPW   32                  // scenes in flight (32 x 2MB = 64MB, fits L2)
#define CPS   8                   // CTAs per scene
#define NCTA  (SPW*CPS)           // 256 — co-resident at 2 CTAs/SM (296 slots)
#define THREADS 256
#define NWARP 8
#define CHUNK (OBJS_/CPS)         // 256 rows per CTA
#define RPW   (CHUNK/NWARP)       // 32 rows per warp

typedef unsigned long long u64;

// Scratch (device globals — allocation-free rule). Per-(scene,chunk) slots,
// plain stores; counters are reset by each scene's finalizer -> replay-safe.
__device__ float g_ctxp [B_*CPS*D_];     // column-sum partials
__device__ float g_featp[B_*CPS*D_*K_];  // pooled-feature partials
__device__ float g_zsump[B_*CPS*K_];     // zsum partials
__device__ float g_z[NK];                // unnormalized numerators (staging)
__device__ int   g_cntA[B_];             // per-scene pass-1 arrivals
__device__ int   g_cntB[B_];             // per-scene pass-2 completions

// ---- packed f32x2 helpers --------------------------------------------------
__device__ __forceinline__ u64 pack2(float lo, float hi) {
    u64 r; asm("mov.b64 %0,{%1,%2};" : "=l"(r) : "f"(lo), "f"(hi)); return r;
}
__device__ __forceinline__ float2 unpack2(u64 v) {
    float lo, hi; asm("mov.b64 {%0,%1},%2;" : "=f"(lo), "=f"(hi) : "l"(v));
    return make_float2(lo, hi);
}
__device__ __forceinline__ u64 add2(u64 a, u64 b) {
    u64 d; asm("add.rn.f32x2 %0,%1,%2;" : "=l"(d) : "l"(a), "l"(b)); return d;
}
__device__ __forceinline__ u64 fma2(u64 a, u64 b, u64 c) {
    u64 d; asm("fma.rn.f32x2 %0,%1,%2,%3;" : "=l"(d) : "l"(a), "l"(b), "l"(c)); return d;
}
__device__ __forceinline__ u64 abs2(u64 a) {
    u64 d; asm("and.b64 %0,%1,0x7FFFFFFF7FFFFFFF;" : "=l"(d) : "l"(a)); return d;
}

// ---------------------------------------------------------------------------
// 256 fully-resident CTAs; each handles one 256-row chunk of one scene per
// wave. Sync is PER-SCENE only (8 resident CTAs, arrive-then-wait) -> scenes
// drift independently, overlapping DRAM p1 with L2 p2 across the grid.
// ---------------------------------------------------------------------------
__global__ __launch_bounds__(THREADS, 2) void fusedK(
    const float* __restrict__ x,
    const float* __restrict__ att,
    const float* __restrict__ scale,
    const float* __restrict__ cb,
    const int*   __restrict__ num_objs,
    float*       __restrict__ out,
    int out_size)
{
    __shared__ __align__(16) float sred[4*D_];      // p1 rowgroup partials (4 KB)
    __shared__ __align__(16) float sctx[D_];        // scene mean context
    __shared__ float sfeat[D_*K_];                  // feature accum (2 KB)
    __shared__ __align__(8) float sz[CHUNK*K_];     // per-row z (2 KB)
    __shared__ float sbt[K_];
    __shared__ float szs[K_];
    __shared__ int   slast;

    const int cta   = blockIdx.x;
    const int sidx  = cta >> 3;           // scene slot (0..31)
    const int chunk = cta & 7;
    const int tid   = threadIdx.x;
    const int warp  = tid >> 5, lane = tid & 31;
    const int col4  = tid & 63, rg = tid >> 6;      // p1: 64 cols x 4 rowgroups

    const bool full_out = (out_size >= BDK + NK);
    const bool attn_any = full_out || (out_size == NK);

    // bias_term (tiny, per-CTA redundant)
    if (tid < 64) {
        int k = tid >> 5, l = tid & 31;
        float s = 0.f;
        #pragma unroll
        for (int j = 0; j < 8; j++) s += cb[k*D_ + l + 32*j] * att[l + 32*j];
        #pragma unroll
        for (int m = 16; m; m >>= 1) s += __shfl_xor_sync(0xffffffffu, s, m);
        if (l == 0) sbt[k] = s;
    }

    // per-lane invariant att factors: lrelu(t)=0.6t+0.4|t|
    float4 a_a = ((const float4*)att)[lane];
    float4 a_b = ((const float4*)att)[lane + 32];
    const u64 a6_0 = pack2(0.6f*a_a.x, 0.6f*a_a.y), a6_1 = pack2(0.6f*a_a.z, 0.6f*a_a.w);
    const u64 a6_2 = pack2(0.6f*a_b.x, 0.6f*a_b.y), a6_3 = pack2(0.6f*a_b.z, 0.6f*a_b.w);
    const u64 a4_0 = pack2(0.4f*a_a.x, 0.4f*a_a.y), a4_1 = pack2(0.4f*a_a.z, 0.4f*a_a.w);
    const u64 a4_2 = pack2(0.4f*a_b.x, 0.4f*a_b.y), a4_3 = pack2(0.4f*a_b.z, 0.4f*a_b.w);

    #pragma unroll 1
    for (int w = 0; w < WAVES; w++) {
        const int b = w*SPW + sidx;                 // global scene id

        // ========== pass 1: column sums, 4-deep batched loads ==============
        {
            // rows rg, rg+4, rg+8, ... (64 rows per rowgroup), batched 4 deep
            const float4* p = (const float4*)x
                + ((size_t)(b*OBJS_ + chunk*CHUNK + rg))*64 + col4;
            float4 acc0 = {0.f,0.f,0.f,0.f}, acc1 = {0.f,0.f,0.f,0.f};
            #pragma unroll
            for (int i = 0; i < 16; i++) {
                float4 v0 = p[(size_t)(16*i +  0)*64];
                float4 v1 = p[(size_t)(16*i +  4)*64];
                float4 v2 = p[(size_t)(16*i +  8)*64];
                float4 v3 = p[(size_t)(16*i + 12)*64];
                acc0.x += v0.x+v1.x; acc0.y += v0.y+v1.y;
                acc0.z += v0.z+v1.z; acc0.w += v0.w+v1.w;
                acc1.x += v2.x+v3.x; acc1.y += v2.y+v3.y;
                acc1.z += v2.z+v3.z; acc1.w += v2.w+v3.w;
            }
            acc0.x += acc1.x; acc0.y += acc1.y; acc0.z += acc1.z; acc0.w += acc1.w;
            *(float4*)&sred[rg*D_ + col4*4] = acc0;
        }
        __syncthreads();
        g_ctxp[(size_t)(b*CPS + chunk)*D_ + tid] =
            sred[tid] + sred[D_+tid] + sred[2*D_+tid] + sred[3*D_+tid];
        for (int i = tid; i < D_*K_; i += THREADS) sfeat[i] = 0.f;
        if (tid < K_) szs[tid] = 0.f;

        // ========== per-scene barrier A (8 resident CTAs) ==================
        __threadfence();
        __syncthreads();
        if (tid == 0) {
            atomicAdd(&g_cntA[b], 1);
            volatile int* c = &g_cntA[b];
            while (*c < CPS) __nanosleep(64);
        }
        __syncthreads();
        __threadfence();

        // scene mean context from the 8 partials (L2-hot)
        {
            const float invc = 1.f / fmaxf((float)num_objs[b], 1.f);
            float s = 0.f;
            #pragma unroll
            for (int j = 0; j < CPS; j++) s += g_ctxp[(size_t)(b*CPS + j)*D_ + tid];
            sctx[tid] = s * invc;
        }
        __syncthreads();

        // ========== pass 2: fused logits + exp + pooling (L2-hot) ==========
        const float bt0 = sbt[0], bt1 = sbt[1];
        const float s0  = scale[0], s1 = scale[1];

        float4 cxa = ((const float4*)sctx)[lane];
        float4 cxb = ((const float4*)sctx)[lane + 32];
        u64 c0 = pack2(cxa.x, cxa.y), c1 = pack2(cxa.z, cxa.w);
        u64 c2 = pack2(cxb.x, cxb.y), c3 = pack2(cxb.z, cxb.w);

        u64 f0_0=0,f0_1=0,f0_2=0,f0_3=0;   // k=0 pooled features (packed)
        u64 f1_0=0,f1_1=0,f1_2=0,f1_3=0;   // k=1
        float zs0 = 0.f, zs1 = 0.f;

        const int rowbase = b*OBJS_ + chunk*CHUNK + warp*RPW;

        #pragma unroll 4
        for (int r = 0; r < RPW; r++) {
            const int lrow = warp*RPW + r;
            const ulonglong2* xr = (const ulonglong2*)(x + (size_t)(rowbase + r)*D_);
            ulonglong2 xa = xr[lane];
            ulonglong2 xb = xr[lane + 32];

            u64 t0 = add2(xa.x, c0), t1 = add2(xa.y, c1);
            u64 t2 = add2(xb.x, c2), t3 = add2(xb.y, c3);
            u64 accA = fma2(a6_0, t0, fma2(a4_0, abs2(t0), 0ull));
            accA     = fma2(a6_1, t1, fma2(a4_1, abs2(t1), accA));
            u64 accB = fma2(a6_2, t2, fma2(a4_2, abs2(t2), 0ull));
            accB     = fma2(a6_3, t3, fma2(a4_3, abs2(t3), accB));
            float2 p = unpack2(add2(accA, accB));
            float acc = p.x + p.y;
            #pragma unroll
            for (int m = 16; m; m >>= 1)
                acc += __shfl_xor_sync(0xffffffffu, acc, m);

            float z0 = __expf((acc + bt0) * s0);
            float z1 = __expf((acc + bt1) * s1);
            zs0 += z0; zs1 += z1;
            if (lane == 0) *(float2*)&sz[lrow*2] = make_float2(z0, z1);

            u64 zz0 = pack2(z0, z0), zz1 = pack2(z1, z1);
            f0_0 = fma2(xa.x, zz0, f0_0); f0_1 = fma2(xa.y, zz0, f0_1);
            f0_2 = fma2(xb.x, zz0, f0_2); f0_3 = fma2(xb.y, zz0, f0_3);
            f1_0 = fma2(xa.x, zz1, f1_0); f1_1 = fma2(xa.y, zz1, f1_1);
            f1_2 = fma2(xb.x, zz1, f1_2); f1_3 = fma2(xb.y, zz1, f1_3);
        }

        // cross-warp combine (lanes hit distinct smem addrs within a warp)
        {
            int d0 = 4*lane, d1 = 128 + 4*lane;
            float2 v;
            v = unpack2(f0_0); atomicAdd(&sfeat[(d0+0)*2+0], v.x); atomicAdd(&sfeat[(d0+1)*2+0], v.y);
            v = unpack2(f0_1); atomicAdd(&sfeat[(d0+2)*2+0], v.x); atomicAdd(&sfeat[(d0+3)*2+0], v.y);
            v = unpack2(f0_2); atomicAdd(&sfeat[(d1+0)*2+0], v.x); atomicAdd(&sfeat[(d1+1)*2+0], v.y);
            v = unpack2(f0_3); atomicAdd(&sfeat[(d1+2)*2+0], v.x); atomicAdd(&sfeat[(d1+3)*2+0], v.y);
            v = unpack2(f1_0); atomicAdd(&sfeat[(d0+0)*2+1], v.x); atomicAdd(&sfeat[(d0+1)*2+1], v.y);
            v = unpack2(f1_1); atomicAdd(&sfeat[(d0+2)*2+1], v.x); atomicAdd(&sfeat[(d0+3)*2+1], v.y);
            v = unpack2(f1_2); atomicAdd(&sfeat[(d1+0)*2+1], v.x); atomicAdd(&sfeat[(d1+1)*2+1], v.y);
            v = unpack2(f1_3); atomicAdd(&sfeat[(d1+2)*2+1], v.x); atomicAdd(&sfeat[(d1+3)*2+1], v.y);
        }
        if (lane == 0) { atomicAdd(&szs[0], zs0); atomicAdd(&szs[1], zs1); }
        __syncthreads();

        // publish per-(scene,chunk) partials + z staging (plain stores)
        const int slot = b*CPS + chunk;
        for (int i = tid; i < D_*K_; i += THREADS)
            g_featp[(size_t)slot*(D_*K_) + i] = sfeat[i];
        if (tid < K_) g_zsump[slot*K_ + tid] = szs[tid];
        {
            float2* gz2 = ((float2*)g_z) + b*OBJS_ + chunk*CHUNK;
            const float2* z2 = (const float2*)sz;
            for (int i = tid; i < CHUNK; i += THREADS) gz2[i] = z2[i];
        }

        // ========== per-scene completion: last CTA finalizes ===============
        __threadfence();
        __syncthreads();
        if (tid == 0) slast = (atomicAdd(&g_cntB[b], 1) == CPS-1);
        __syncthreads();

        if (slast) {
            __threadfence();
            float zt0 = 0.f, zt1 = 0.f;
            #pragma unroll
            for (int j = 0; j < CPS; j++) {
                zt0 += g_zsump[(b*CPS + j)*K_ + 0];
                zt1 += g_zsump[(b*CPS + j)*K_ + 1];
            }
            const float inv0 = 1.f/zt0, inv1 = 1.f/zt1;

            if (out_size >= BDK) {             // features [B,D,K] at offset 0
                for (int e = tid; e < D_*K_; e += THREADS) {
                    float s = 0.f;
                    #pragma unroll
                    for (int j = 0; j < CPS; j++)
                        s += g_featp[(size_t)(b*CPS + j)*(D_*K_) + e];
                    out[b*(D_*K_) + e] = s * ((e & 1) ? inv1 : inv0);
                }
            }
            if (attn_any) {                    // attention weights [N,K]
                int obase = full_out ? (BDK/2) : 0;
                const float2* gz2 = ((const float2*)g_z) + b*OBJS_;
                float2* o2 = ((float2*)out) + obase + b*OBJS_;
                for (int i = tid; i < OBJS_; i += THREADS) {
                    float2 z = gz2[i];
                    o2[i] = make_float2(z.x*inv0, z.y*inv1);
                }
            }
            __syncthreads();                   // all reads done before reset
            if (tid == 0) { g_cntA[b] = 0; g_cntB[b] = 0; }  // replay-safe
        }
        __syncthreads();   // sz/sred reuse ordering before next wave
    }
}

// ---------------------------------------------------------------------------
extern "C" void kernel_launch(void* const* d_in, const int* in_sizes, int n_in,
                              void* d_out, int out_size)
{
    const float* x        = (const float*)d_in[0];  // [N, D]
    const int*   num_objs = (const int*)  d_in[1];  // [B]
    const float* att      = (const float*)d_in[2];  // [1, D]
    const float* scale    = (const float*)d_in[3];  // [K, 1]
    const float* cb       = (const float*)d_in[4];  // [K, D]
    float*       out      = (float*)d_out;

    fusedK<<<NCTA, THREADS>>>(x, att, scale, cb, num_objs, out, out_size);
}